// round 2
// baseline (speedup 1.0000x reference)
#include <cuda_runtime.h>
#include <cstdint>
#include <cstddef>

// Problem constants
#define BATCH   4
#define SLEN    4096
#define DDIM    1024
#define MTOT    (BATCH * SLEN)          // 16384

// Scratch buffers (allocation-free rule: __device__ globals)
__device__ float g_Q[(size_t)BATCH * SLEN * DDIM];   // 64 MB
__device__ float g_K[(size_t)BATCH * SLEN * DDIM];   // 64 MB
__device__ float g_V[(size_t)BATCH * SLEN * DDIM];   // 64 MB
__device__ float g_S[(size_t)BATCH * SLEN * SLEN];   // 256 MB

// ---------------------------------------------------------------------------
// Tiled GEMM, NT form: C[m,n] = sum_k A[m,k] * B[n,k]
// BM=BN=128, BK=16, 256 threads, 8x8 per thread. All dims assumed divisible.
// blockIdx.z indexes batch via strides.
// ---------------------------------------------------------------------------
__global__ __launch_bounds__(256) void gemm_nt(
    const float* __restrict__ A, const float* __restrict__ B, float* __restrict__ C,
    int M, int N, int K, size_t sA, size_t sB, size_t sC)
{
    A += (size_t)blockIdx.z * sA;
    B += (size_t)blockIdx.z * sB;
    C += (size_t)blockIdx.z * sC;

    __shared__ float As[16][128];
    __shared__ float Bs[16][128];

    const int tid = threadIdx.x;
    const int tx  = tid & 15;        // 0..15 -> N direction
    const int ty  = tid >> 4;        // 0..15 -> M direction
    const int bm  = blockIdx.y * 128;
    const int bn  = blockIdx.x * 128;

    // load mapping: 128 rows x 16 cols per tile; each thread: 2 float4
    const int lr = tid >> 2;         // 0..63
    const int lc = (tid & 3) << 2;   // 0,4,8,12

    const float* Aptr = A + (size_t)(bm + lr) * K + lc;
    const float* Bptr = B + (size_t)(bn + lr) * K + lc;

    float acc[8][8];
    #pragma unroll
    for (int i = 0; i < 8; i++)
        #pragma unroll
        for (int j = 0; j < 8; j++) acc[i][j] = 0.0f;

    for (int k0 = 0; k0 < K; k0 += 16) {
        float4 a0 = *(const float4*)(Aptr + k0);
        float4 a1 = *(const float4*)(Aptr + (size_t)64 * K + k0);
        float4 b0 = *(const float4*)(Bptr + k0);
        float4 b1 = *(const float4*)(Bptr + (size_t)64 * K + k0);

        As[lc + 0][lr]      = a0.x; As[lc + 1][lr]      = a0.y;
        As[lc + 2][lr]      = a0.z; As[lc + 3][lr]      = a0.w;
        As[lc + 0][lr + 64] = a1.x; As[lc + 1][lr + 64] = a1.y;
        As[lc + 2][lr + 64] = a1.z; As[lc + 3][lr + 64] = a1.w;

        Bs[lc + 0][lr]      = b0.x; Bs[lc + 1][lr]      = b0.y;
        Bs[lc + 2][lr]      = b0.z; Bs[lc + 3][lr]      = b0.w;
        Bs[lc + 0][lr + 64] = b1.x; Bs[lc + 1][lr + 64] = b1.y;
        Bs[lc + 2][lr + 64] = b1.z; Bs[lc + 3][lr + 64] = b1.w;

        __syncthreads();

        #pragma unroll
        for (int k = 0; k < 16; k++) {
            float a[8], b[8];
            *(float4*)(a)     = *(const float4*)&As[k][ty * 8];
            *(float4*)(a + 4) = *(const float4*)&As[k][ty * 8 + 4];
            *(float4*)(b)     = *(const float4*)&Bs[k][tx * 8];
            *(float4*)(b + 4) = *(const float4*)&Bs[k][tx * 8 + 4];
            #pragma unroll
            for (int i = 0; i < 8; i++)
                #pragma unroll
                for (int j = 0; j < 8; j++)
                    acc[i][j] += a[i] * b[j];
        }
        __syncthreads();
    }

    #pragma unroll
    for (int i = 0; i < 8; i++) {
        float* Crow = C + (size_t)(bm + ty * 8 + i) * N + bn + tx * 8;
        *(float4*)(Crow)     = make_float4(acc[i][0], acc[i][1], acc[i][2], acc[i][3]);
        *(float4*)(Crow + 4) = make_float4(acc[i][4], acc[i][5], acc[i][6], acc[i][7]);
    }
}

// ---------------------------------------------------------------------------
// Tiled GEMM, NN form: C[m,n] = sum_k A[m,k] * B[k,n]
// ---------------------------------------------------------------------------
__global__ __launch_bounds__(256) void gemm_nn(
    const float* __restrict__ A, const float* __restrict__ B, float* __restrict__ C,
    int M, int N, int K, size_t sA, size_t sB, size_t sC)
{
    A += (size_t)blockIdx.z * sA;
    B += (size_t)blockIdx.z * sB;
    C += (size_t)blockIdx.z * sC;

    __shared__ float As[16][128];
    __shared__ float Bs[16][128];

    const int tid = threadIdx.x;
    const int tx  = tid & 15;
    const int ty  = tid >> 4;
    const int bm  = blockIdx.y * 128;
    const int bn  = blockIdx.x * 128;

    // A tile: 128 rows x 16 k (transpose into As)
    const int lr = tid >> 2;
    const int lc = (tid & 3) << 2;
    const float* Aptr = A + (size_t)(bm + lr) * K + lc;

    // B tile: 16 k-rows x 128 n-cols (direct copy)
    const int br = tid >> 5;          // 0..7
    const int bc = (tid & 31) << 2;   // 0..124

    float acc[8][8];
    #pragma unroll
    for (int i = 0; i < 8; i++)
        #pragma unroll
        for (int j = 0; j < 8; j++) acc[i][j] = 0.0f;

    for (int k0 = 0; k0 < K; k0 += 16) {
        float4 a0 = *(const float4*)(Aptr + k0);
        float4 a1 = *(const float4*)(Aptr + (size_t)64 * K + k0);
        float4 v0 = *(const float4*)(B + (size_t)(k0 + br) * N + bn + bc);
        float4 v1 = *(const float4*)(B + (size_t)(k0 + br + 8) * N + bn + bc);

        As[lc + 0][lr]      = a0.x; As[lc + 1][lr]      = a0.y;
        As[lc + 2][lr]      = a0.z; As[lc + 3][lr]      = a0.w;
        As[lc + 0][lr + 64] = a1.x; As[lc + 1][lr + 64] = a1.y;
        As[lc + 2][lr + 64] = a1.z; As[lc + 3][lr + 64] = a1.w;

        *(float4*)&Bs[br][bc]     = v0;
        *(float4*)&Bs[br + 8][bc] = v1;

        __syncthreads();

        #pragma unroll
        for (int k = 0; k < 16; k++) {
            float a[8], b[8];
            *(float4*)(a)     = *(const float4*)&As[k][ty * 8];
            *(float4*)(a + 4) = *(const float4*)&As[k][ty * 8 + 4];
            *(float4*)(b)     = *(const float4*)&Bs[k][tx * 8];
            *(float4*)(b + 4) = *(const float4*)&Bs[k][tx * 8 + 4];
            #pragma unroll
            for (int i = 0; i < 8; i++)
                #pragma unroll
                for (int j = 0; j < 8; j++)
                    acc[i][j] += a[i] * b[j];
        }
        __syncthreads();
    }

    #pragma unroll
    for (int i = 0; i < 8; i++) {
        float* Crow = C + (size_t)(bm + ty * 8 + i) * N + bn + tx * 8;
        *(float4*)(Crow)     = make_float4(acc[i][0], acc[i][1], acc[i][2], acc[i][3]);
        *(float4*)(Crow + 4) = make_float4(acc[i][4], acc[i][5], acc[i][6], acc[i][7]);
    }
}

// ---------------------------------------------------------------------------
// Row softmax over 4096 columns. One block (256 threads) per row.
// ---------------------------------------------------------------------------
__global__ __launch_bounds__(256) void softmax_kernel(float* __restrict__ Sm)
{
    float* row = Sm + (size_t)blockIdx.x * SLEN;
    const int t    = threadIdx.x;
    const int lane = t & 31;
    const int warp = t >> 5;

    __shared__ float red[8];

    float v[16];
    float mx = -1e30f;
    #pragma unroll
    for (int i = 0; i < 16; i++) {
        v[i] = row[t + (i << 8)];
        mx = fmaxf(mx, v[i]);
    }
    #pragma unroll
    for (int o = 16; o > 0; o >>= 1)
        mx = fmaxf(mx, __shfl_xor_sync(0xffffffffu, mx, o));
    if (lane == 0) red[warp] = mx;
    __syncthreads();
    float rmax = red[0];
    #pragma unroll
    for (int i = 1; i < 8; i++) rmax = fmaxf(rmax, red[i]);

    float sum = 0.0f;
    #pragma unroll
    for (int i = 0; i < 16; i++) {
        v[i] = __expf(v[i] - rmax);
        sum += v[i];
    }
    #pragma unroll
    for (int o = 16; o > 0; o >>= 1)
        sum += __shfl_xor_sync(0xffffffffu, sum, o);
    __syncthreads();                // red[] reads for max are done
    if (lane == 0) red[warp] = sum;
    __syncthreads();
    float rsum = 0.0f;
    #pragma unroll
    for (int i = 0; i < 8; i++) rsum += red[i];

    const float inv = 1.0f / rsum;
    #pragma unroll
    for (int i = 0; i < 16; i++)
        row[t + (i << 8)] = v[i] * inv;
}

// ---------------------------------------------------------------------------
// Epilogue: y = attended + x;  out = y / ||y||_2 (per 1024-row).
// One block (256 threads) per row; out currently holds `attended`.
// ---------------------------------------------------------------------------
__global__ __launch_bounds__(256) void epilogue_kernel(
    const float* __restrict__ x, float* __restrict__ out)
{
    const size_t base = (size_t)blockIdx.x * DDIM;
    const int t    = threadIdx.x;
    const int lane = t & 31;
    const int warp = t >> 5;

    __shared__ float red[8];

    float4 a  = *(const float4*)(out + base + t * 4);
    float4 xv = *(const float4*)(x   + base + t * 4);
    float y0 = a.x + xv.x;
    float y1 = a.y + xv.y;
    float y2 = a.z + xv.z;
    float y3 = a.w + xv.w;

    float ss = y0 * y0 + y1 * y1 + y2 * y2 + y3 * y3;
    #pragma unroll
    for (int o = 16; o > 0; o >>= 1)
        ss += __shfl_xor_sync(0xffffffffu, ss, o);
    if (lane == 0) red[warp] = ss;
    __syncthreads();
    float tot = 0.0f;
    #pragma unroll
    for (int i = 0; i < 8; i++) tot += red[i];

    const float inv = 1.0f / sqrtf(tot);
    *(float4*)(out + base + t * 4) =
        make_float4(y0 * inv, y1 * inv, y2 * inv, y3 * inv);
}

// ---------------------------------------------------------------------------
// Launch
// ---------------------------------------------------------------------------
extern "C" void kernel_launch(void* const* d_in, const int* in_sizes, int n_in,
                              void* d_out, int out_size)
{
    const float* x  = (const float*)d_in[0];
    const float* Wq = (const float*)d_in[1];
    const float* Wk = (const float*)d_in[2];
    const float* Wv = (const float*)d_in[3];
    float* out = (float*)d_out;

    float *Q, *K, *V, *Sc;
    cudaGetSymbolAddress((void**)&Q,  g_Q);
    cudaGetSymbolAddress((void**)&K,  g_K);
    cudaGetSymbolAddress((void**)&V,  g_V);
    cudaGetSymbolAddress((void**)&Sc, g_S);

    const size_t sQKV = (size_t)SLEN * DDIM;   // per-batch stride in Q/K/V
    const size_t sSS  = (size_t)SLEN * SLEN;   // per-batch stride in scores

    dim3 blk(256);

    // QKV projections: [16384,1024] = x[16384,1024] @ W^T   (NT)
    dim3 gqkv(DDIM / 128, MTOT / 128, 1);      // (8, 128, 1)
    gemm_nt<<<gqkv, blk>>>(x, Wq, Q, MTOT, DDIM, DDIM, 0, 0, 0);
    gemm_nt<<<gqkv, blk>>>(x, Wk, K, MTOT, DDIM, DDIM, 0, 0, 0);
    gemm_nt<<<gqkv, blk>>>(x, Wv, V, MTOT, DDIM, DDIM, 0, 0, 0);

    // scores = Q @ K^T per batch   (NT, batched over z)
    dim3 gsc(SLEN / 128, SLEN / 128, BATCH);   // (32, 32, 4)
    gemm_nt<<<gsc, blk>>>(Q, K, Sc, SLEN, SLEN, DDIM, sQKV, sQKV, sSS);

    // softmax over rows (BETA = 1)
    softmax_kernel<<<MTOT, blk>>>(Sc);

    // attended = P @ V per batch   (NN), written straight into d_out
    dim3 gav(DDIM / 128, SLEN / 128, BATCH);   // (8, 32, 4)
    gemm_nn<<<gav, blk>>>(Sc, V, out, SLEN, DDIM, SLEN, sSS, sQKV, sQKV);

    // y = attended + x; L2 normalize
    epilogue_kernel<<<MTOT, blk>>>(x, out);
}

// round 4
// speedup vs baseline: 2.6509x; 2.6509x over previous
#include <cuda_runtime.h>
#include <cuda_bf16.h>
#include <cstdint>
#include <cstddef>

#define BATCH   4
#define SLEN    4096
#define DDIM    1024
#define MTOT    (BATCH * SLEN)          // 16384

// Scratch (allocation-free rule: __device__ globals)
__device__ float g_Q[(size_t)BATCH * SLEN * DDIM];   // 64 MB
__device__ float g_K[(size_t)BATCH * SLEN * DDIM];   // 64 MB
__device__ float g_V[(size_t)BATCH * SLEN * DDIM];   // 64 MB (V transposed [D, MTOT])
__device__ float g_S[(size_t)BATCH * SLEN * SLEN];   // 256 MB

// ---------------------------------------------------------------------------
// Warp-level MMA helpers (arch-agnostic PTX: works on plain sm_103 target)
// ---------------------------------------------------------------------------
__device__ __forceinline__ uint32_t smem_u32(const void* p) {
    uint32_t a;
    asm("{ .reg .u64 t; cvta.to.shared.u64 t, %1; cvt.u32.u64 %0, t; }" : "=r"(a) : "l"(p));
    return a;
}

__device__ __forceinline__ void ldsm4(uint32_t& r0, uint32_t& r1, uint32_t& r2, uint32_t& r3,
                                      uint32_t addr) {
    asm volatile("ldmatrix.sync.aligned.m8n8.x4.shared.b16 {%0,%1,%2,%3}, [%4];"
                 : "=r"(r0), "=r"(r1), "=r"(r2), "=r"(r3) : "r"(addr));
}

__device__ __forceinline__ void mma16816(float* c, const uint32_t* a, const uint32_t* b) {
    asm volatile(
        "mma.sync.aligned.m16n8k16.row.col.f32.bf16.bf16.f32 "
        "{%0,%1,%2,%3}, {%4,%5,%6,%7}, {%8,%9}, {%0,%1,%2,%3};"
        : "+f"(c[0]), "+f"(c[1]), "+f"(c[2]), "+f"(c[3])
        : "r"(a[0]), "r"(a[1]), "r"(a[2]), "r"(a[3]), "r"(b[0]), "r"(b[1]));
}

// ---------------------------------------------------------------------------
// NT GEMM on tensor cores (HMMA), bf16 3-pass fp32 emulation.
// C[m,n] = sum_k A[m,k] * B[n,k].  Tile 128x128x32, 256 threads, double-buffered.
// transC: C stored transposed (C[n*ldc + m]).
// ---------------------------------------------------------------------------
#define LDT       40                        // padded row stride (bf16 elems) -> 80 B
#define MAT_B     (128 * LDT * 2)           // 10240 B per matrix tile
#define STAGE_B   (4 * MAT_B)               // Ahi, Alo, Bhi, Blo
#define SMEM_DYN  (2 * STAGE_B)             // 81920 B

__global__ __launch_bounds__(256, 1) void gemm_tc(
    const float* __restrict__ A, const float* __restrict__ B, float* __restrict__ C,
    int lda, int ldb, int ldc, int K, int transC,
    size_t sA, size_t sB, size_t sC)
{
    extern __shared__ char smem[];
    A += (size_t)blockIdx.z * sA;
    B += (size_t)blockIdx.z * sB;
    C += (size_t)blockIdx.z * sC;

    const int tid  = threadIdx.x;
    const int lane = tid & 31;
    const int wid  = tid >> 5;
    const int bm   = blockIdx.y * 128;
    const int bn   = blockIdx.x * 128;
    const int m_warp = (wid & 3) * 32;      // 4 warps along M
    const int n_warp = (wid >> 2) * 64;     // 2 warps along N

    const uint32_t sbase = smem_u32(smem);

    // global-load mapping: 128 rows x 8 float4-cols per matrix, 4 iters/thread
    int lr[4], lc[4];
    #pragma unroll
    for (int i = 0; i < 4; i++) {
        int l = tid + i * 256;
        lr[i] = l >> 3;
        lc[i] = (l & 7) * 4;                // fp32 col
    }

    // ldmatrix per-lane offsets (bytes)
    const uint32_t aoff = (uint32_t)((m_warp + (lane & 15)) * (LDT * 2) + ((lane >> 4) * 8) * 2);
    const uint32_t boff = (uint32_t)((n_warp + (lane & 7) + ((lane & 16) ? 8 : 0)) * (LDT * 2)
                                     + ((lane & 8) ? 8 : 0) * 2);

    float acc[2][8][4];
    #pragma unroll
    for (int t = 0; t < 2; t++)
        #pragma unroll
        for (int n = 0; n < 8; n++)
            #pragma unroll
            for (int q = 0; q < 4; q++) acc[t][n][q] = 0.0f;

    const int nk = K / 32;
    float4 va[4], vb[4];

    // ---- helpers as lambdas ----
    auto load_chunk = [&](int c) {
        const int k0 = c * 32;
        #pragma unroll
        for (int i = 0; i < 4; i++) {
            va[i] = *(const float4*)(A + (size_t)(bm + lr[i]) * lda + k0 + lc[i]);
            vb[i] = *(const float4*)(B + (size_t)(bn + lr[i]) * ldb + k0 + lc[i]);
        }
    };

    auto sts_chunk = [&](int s) {
        char* st = smem + s * STAGE_B;
        #pragma unroll
        for (int i = 0; i < 4; i++) {
            const uint32_t off = (uint32_t)(lr[i] * (LDT * 2) + (lc[i]) * 2);  // bytes
            // A
            {
                float4 v = va[i];
                __nv_bfloat162 h0 = __floats2bfloat162_rn(v.x, v.y);
                __nv_bfloat162 h1 = __floats2bfloat162_rn(v.z, v.w);
                float2 f0 = __bfloat1622float2(h0);
                float2 f1 = __bfloat1622float2(h1);
                __nv_bfloat162 e0 = __floats2bfloat162_rn(v.x - f0.x, v.y - f0.y);
                __nv_bfloat162 e1 = __floats2bfloat162_rn(v.z - f1.x, v.w - f1.y);
                union { __nv_bfloat162 h[2]; uint2 u; } cv;
                cv.h[0] = h0; cv.h[1] = h1;
                *(uint2*)(st + 0 * MAT_B + off) = cv.u;
                cv.h[0] = e0; cv.h[1] = e1;
                *(uint2*)(st + 1 * MAT_B + off) = cv.u;
            }
            // B
            {
                float4 v = vb[i];
                __nv_bfloat162 h0 = __floats2bfloat162_rn(v.x, v.y);
                __nv_bfloat162 h1 = __floats2bfloat162_rn(v.z, v.w);
                float2 f0 = __bfloat1622float2(h0);
                float2 f1 = __bfloat1622float2(h1);
                __nv_bfloat162 e0 = __floats2bfloat162_rn(v.x - f0.x, v.y - f0.y);
                __nv_bfloat162 e1 = __floats2bfloat162_rn(v.z - f1.x, v.w - f1.y);
                union { __nv_bfloat162 h[2]; uint2 u; } cv;
                cv.h[0] = h0; cv.h[1] = h1;
                *(uint2*)(st + 2 * MAT_B + off) = cv.u;
                cv.h[0] = e0; cv.h[1] = e1;
                *(uint2*)(st + 3 * MAT_B + off) = cv.u;
            }
        }
    };

    auto compute_chunk = [&](int s) {
        const uint32_t base = sbase + s * STAGE_B;
        #pragma unroll
        for (int ks = 0; ks < 2; ks++) {
            const uint32_t kb = ks * 32;            // 16 bf16 * 2 B
            uint32_t ah[2][4], al[2][4], bh[4][4], bl[4][4];
            #pragma unroll
            for (int t = 0; t < 2; t++) {
                uint32_t a0 = base + 0 * MAT_B + aoff + t * (16 * LDT * 2) + kb;
                ldsm4(ah[t][0], ah[t][1], ah[t][2], ah[t][3], a0);
                uint32_t a1 = base + 1 * MAT_B + aoff + t * (16 * LDT * 2) + kb;
                ldsm4(al[t][0], al[t][1], al[t][2], al[t][3], a1);
            }
            #pragma unroll
            for (int u = 0; u < 4; u++) {
                uint32_t b0 = base + 2 * MAT_B + boff + u * (16 * LDT * 2) + kb;
                ldsm4(bh[u][0], bh[u][1], bh[u][2], bh[u][3], b0);
                uint32_t b1 = base + 3 * MAT_B + boff + u * (16 * LDT * 2) + kb;
                ldsm4(bl[u][0], bl[u][1], bl[u][2], bl[u][3], b1);
            }
            #pragma unroll
            for (int t = 0; t < 2; t++)
                #pragma unroll
                for (int n = 0; n < 8; n++) {
                    const uint32_t* fh = &bh[n >> 1][(n & 1) * 2];
                    const uint32_t* fl = &bl[n >> 1][(n & 1) * 2];
                    mma16816(acc[t][n], ah[t], fh);   // hi*hi
                    mma16816(acc[t][n], ah[t], fl);   // hi*lo
                    mma16816(acc[t][n], al[t], fh);   // lo*hi
                }
        }
    };

    // ---- pipeline ----
    load_chunk(0);
    sts_chunk(0);
    __syncthreads();

    for (int c = 0; c < nk; ++c) {
        const int s = c & 1;
        if (c + 1 < nk) load_chunk(c + 1);
        compute_chunk(s);
        __syncthreads();
        if (c + 1 < nk) {
            sts_chunk(s ^ 1);
            __syncthreads();
        }
    }

    // ---- epilogue ----
    #pragma unroll
    for (int t = 0; t < 2; t++)
        #pragma unroll
        for (int n = 0; n < 8; n++) {
            const int row = bm + m_warp + t * 16 + (lane >> 2);
            const int col = bn + n_warp + n * 8 + (lane & 3) * 2;
            if (!transC) {
                *(float2*)(C + (size_t)row * ldc + col) =
                    make_float2(acc[t][n][0], acc[t][n][1]);
                *(float2*)(C + (size_t)(row + 8) * ldc + col) =
                    make_float2(acc[t][n][2], acc[t][n][3]);
            } else {
                C[(size_t)col       * ldc + row]     = acc[t][n][0];
                C[(size_t)(col + 1) * ldc + row]     = acc[t][n][1];
                C[(size_t)col       * ldc + row + 8] = acc[t][n][2];
                C[(size_t)(col + 1) * ldc + row + 8] = acc[t][n][3];
            }
        }
}

// ---------------------------------------------------------------------------
// Row softmax over 4096 columns. One block (256 threads) per row.
// ---------------------------------------------------------------------------
__global__ __launch_bounds__(256) void softmax_kernel(float* __restrict__ Sm)
{
    float* row = Sm + (size_t)blockIdx.x * SLEN;
    const int t    = threadIdx.x;
    const int lane = t & 31;
    const int warp = t >> 5;

    __shared__ float red[8];

    float v[16];
    float mx = -1e30f;
    #pragma unroll
    for (int i = 0; i < 16; i++) {
        v[i] = row[t + (i << 8)];
        mx = fmaxf(mx, v[i]);
    }
    #pragma unroll
    for (int o = 16; o > 0; o >>= 1)
        mx = fmaxf(mx, __shfl_xor_sync(0xffffffffu, mx, o));
    if (lane == 0) red[warp] = mx;
    __syncthreads();
    float rmax = red[0];
    #pragma unroll
    for (int i = 1; i < 8; i++) rmax = fmaxf(rmax, red[i]);

    float sum = 0.0f;
    #pragma unroll
    for (int i = 0; i < 16; i++) {
        v[i] = __expf(v[i] - rmax);
        sum += v[i];
    }
    #pragma unroll
    for (int o = 16; o > 0; o >>= 1)
        sum += __shfl_xor_sync(0xffffffffu, sum, o);
    __syncthreads();
    if (lane == 0) red[warp] = sum;
    __syncthreads();
    float rsum = 0.0f;
    #pragma unroll
    for (int i = 0; i < 8; i++) rsum += red[i];

    const float inv = 1.0f / rsum;
    #pragma unroll
    for (int i = 0; i < 16; i++)
        row[t + (i << 8)] = v[i] * inv;
}

// ---------------------------------------------------------------------------
// Epilogue: y = attended + x;  out = y / ||y||_2 per 1024-row.
// ---------------------------------------------------------------------------
__global__ __launch_bounds__(256) void epilogue_kernel(
    const float* __restrict__ x, float* __restrict__ out)
{
    const size_t base = (size_t)blockIdx.x * DDIM;
    const int t    = threadIdx.x;
    const int lane = t & 31;
    const int warp = t >> 5;

    __shared__ float red[8];

    float4 a  = *(const float4*)(out + base + t * 4);
    float4 xv = *(const float4*)(x   + base + t * 4);
    float y0 = a.x + xv.x, y1 = a.y + xv.y, y2 = a.z + xv.z, y3 = a.w + xv.w;

    float ss = y0 * y0 + y1 * y1 + y2 * y2 + y3 * y3;
    #pragma unroll
    for (int o = 16; o > 0; o >>= 1)
        ss += __shfl_xor_sync(0xffffffffu, ss, o);
    if (lane == 0) red[warp] = ss;
    __syncthreads();
    float tot = 0.0f;
    #pragma unroll
    for (int i = 0; i < 8; i++) tot += red[i];

    const float inv = 1.0f / sqrtf(tot);
    *(float4*)(out + base + t * 4) =
        make_float4(y0 * inv, y1 * inv, y2 * inv, y3 * inv);
}

// ---------------------------------------------------------------------------
// Launch
// ---------------------------------------------------------------------------
extern "C" void kernel_launch(void* const* d_in, const int* in_sizes, int n_in,
                              void* d_out, int out_size)
{
    const float* x  = (const float*)d_in[0];
    const float* Wq = (const float*)d_in[1];
    const float* Wk = (const float*)d_in[2];
    const float* Wv = (const float*)d_in[3];
    float* out = (float*)d_out;

    float *Q, *K, *Vt, *Sc;
    cudaGetSymbolAddress((void**)&Q,  g_Q);
    cudaGetSymbolAddress((void**)&K,  g_K);
    cudaGetSymbolAddress((void**)&Vt, g_V);
    cudaGetSymbolAddress((void**)&Sc, g_S);

    cudaFuncSetAttribute(gemm_tc, cudaFuncAttributeMaxDynamicSharedMemorySize, SMEM_DYN);

    const size_t sQKV = (size_t)SLEN * DDIM;
    const size_t sSS  = (size_t)SLEN * SLEN;
    dim3 blk(256);

    // Projections (NT): [16384,1024] = x @ W^T;  V written transposed [1024, 16384]
    dim3 gqkv(DDIM / 128, MTOT / 128, 1);
    gemm_tc<<<gqkv, blk, SMEM_DYN>>>(x, Wq, Q,  DDIM, DDIM, DDIM, DDIM, 0, 0, 0, 0);
    gemm_tc<<<gqkv, blk, SMEM_DYN>>>(x, Wk, K,  DDIM, DDIM, DDIM, DDIM, 0, 0, 0, 0);
    gemm_tc<<<gqkv, blk, SMEM_DYN>>>(x, Wv, Vt, DDIM, DDIM, MTOT, DDIM, 1, 0, 0, 0);

    // scores = Q @ K^T per batch (NT)
    dim3 gsc(SLEN / 128, SLEN / 128, BATCH);
    gemm_tc<<<gsc, blk, SMEM_DYN>>>(Q, K, Sc, DDIM, DDIM, SLEN, DDIM, 0, sQKV, sQKV, sSS);

    // softmax (BETA = 1)
    softmax_kernel<<<MTOT, blk>>>(Sc);

    // attended = P @ Vt^T per batch (NT): C[m,d] = sum_s P[m,s] * Vt[d, b*S + s]
    dim3 gav(DDIM / 128, SLEN / 128, BATCH);
    gemm_tc<<<gav, blk, SMEM_DYN>>>(Sc, Vt, out, SLEN, MTOT, DDIM, SLEN, 0,
                                    sSS, (size_t)SLEN, sQKV);

    // y = attended + x; L2 normalize
    epilogue_kernel<<<MTOT, blk>>>(x, out);
}

// round 5
// speedup vs baseline: 2.6942x; 1.0164x over previous
#include <cuda_runtime.h>
#include <cuda_bf16.h>
#include <cstdint>
#include <cstddef>

#define BATCH   4
#define SLEN    4096
#define DDIM    1024
#define MTOT    (BATCH * SLEN)          // 16384

typedef __nv_bfloat16  bf16;
typedef __nv_bfloat162 bf162;

// ---------------------------------------------------------------------------
// Scratch (allocation-free rule: __device__ globals). All operands pre-split
// into bf16 hi/lo pairs so GEMM mainloops are pure bf16.
// ---------------------------------------------------------------------------
__device__ bf16 g_xhi [(size_t)MTOT * DDIM];
__device__ bf16 g_xlo [(size_t)MTOT * DDIM];
__device__ bf16 g_Wqhi[(size_t)DDIM * DDIM];
__device__ bf16 g_Wqlo[(size_t)DDIM * DDIM];
__device__ bf16 g_Wkhi[(size_t)DDIM * DDIM];
__device__ bf16 g_Wklo[(size_t)DDIM * DDIM];
__device__ bf16 g_Wvhi[(size_t)DDIM * DDIM];
__device__ bf16 g_Wvlo[(size_t)DDIM * DDIM];
__device__ bf16 g_Qhi [(size_t)MTOT * DDIM];
__device__ bf16 g_Qlo [(size_t)MTOT * DDIM];
__device__ bf16 g_Khi [(size_t)MTOT * DDIM];
__device__ bf16 g_Klo [(size_t)MTOT * DDIM];
__device__ bf16 g_Vthi[(size_t)DDIM * MTOT];   // V transposed [D, MTOT]
__device__ bf16 g_Vtlo[(size_t)DDIM * MTOT];
__device__ float g_S  [(size_t)MTOT * SLEN];   // fp32 scores (softmax input)
__device__ bf16 g_Phi [(size_t)MTOT * SLEN];
__device__ bf16 g_Plo [(size_t)MTOT * SLEN];

// ---------------------------------------------------------------------------
// Helpers (arch-agnostic PTX only: plain sm_103 target)
// ---------------------------------------------------------------------------
__device__ __forceinline__ uint32_t smem_u32(const void* p) {
    uint32_t a;
    asm("{ .reg .u64 t; cvta.to.shared.u64 t, %1; cvt.u32.u64 %0, t; }" : "=r"(a) : "l"(p));
    return a;
}
__device__ __forceinline__ void ldsm4(uint32_t& r0, uint32_t& r1, uint32_t& r2, uint32_t& r3,
                                      uint32_t addr) {
    asm volatile("ldmatrix.sync.aligned.m8n8.x4.shared.b16 {%0,%1,%2,%3}, [%4];"
                 : "=r"(r0), "=r"(r1), "=r"(r2), "=r"(r3) : "r"(addr));
}
__device__ __forceinline__ void mma16816(float* c, const uint32_t* a, const uint32_t* b) {
    asm volatile(
        "mma.sync.aligned.m16n8k16.row.col.f32.bf16.bf16.f32 "
        "{%0,%1,%2,%3}, {%4,%5,%6,%7}, {%8,%9}, {%0,%1,%2,%3};"
        : "+f"(c[0]), "+f"(c[1]), "+f"(c[2]), "+f"(c[3])
        : "r"(a[0]), "r"(a[1]), "r"(a[2]), "r"(a[3]), "r"(b[0]), "r"(b[1]));
}
__device__ __forceinline__ void cpasync16(uint32_t dst, const void* src) {
    asm volatile("cp.async.cg.shared.global [%0], [%1], 16;" :: "r"(dst), "l"(src));
}
__device__ __forceinline__ void split2(float x, float y, bf162& h, bf162& l) {
    h = __floats2bfloat162_rn(x, y);
    float2 f = __bfloat1622float2(h);
    l = __floats2bfloat162_rn(x - f.x, y - f.y);
}

// ---------------------------------------------------------------------------
// fp32 -> bf16 hi/lo split (elementwise). n divisible by 1024.
// ---------------------------------------------------------------------------
__global__ __launch_bounds__(256) void conv_split(
    const float* __restrict__ src, bf16* __restrict__ hi, bf16* __restrict__ lo)
{
    size_t i = ((size_t)blockIdx.x * 256 + threadIdx.x) * 4;
    float4 v = *(const float4*)(src + i);
    bf162 h0, l0, h1, l1;
    split2(v.x, v.y, h0, l0);
    split2(v.z, v.w, h1, l1);
    *(bf162*)(hi + i)     = h0;
    *(bf162*)(hi + i + 2) = h1;
    *(bf162*)(lo + i)     = l0;
    *(bf162*)(lo + i + 2) = l1;
}

// ---------------------------------------------------------------------------
// Pure-bf16 NT GEMM (3-pass fp32 emulation): C = sum_k A[m,k]*B[n,k]
// Tile 128x128, K-chunk 64, 3-stage cp.async pipeline, 256 threads.
// mode 0: write fp32 Cf.  mode 1: write bf16 hi/lo pair (row-major).
// mode 2: write bf16 hi/lo pair transposed (C[n*ldc+m]).
// ---------------------------------------------------------------------------
#define KC       64
#define LDT      72                         // padded row stride (bf16) -> 144 B
#define MAT_B    (128 * LDT * 2)            // 18432 B
#define STAGE_B  (4 * MAT_B)                // Ahi, Alo, Bhi, Blo = 73728 B
#define NSTAGE   3
#define SMEM_DYN (NSTAGE * STAGE_B)         // 221184 B

__global__ __launch_bounds__(256, 1) void gemm_bf(
    const bf16* __restrict__ Ahi, const bf16* __restrict__ Alo,
    const bf16* __restrict__ Bhi, const bf16* __restrict__ Blo,
    float* __restrict__ Cf, bf16* __restrict__ Chi, bf16* __restrict__ Clo,
    int lda, int ldb, int ldc, int K, int mode,
    size_t sA, size_t sB, size_t sC)
{
    extern __shared__ char smem[];
    Ahi += (size_t)blockIdx.z * sA;  Alo += (size_t)blockIdx.z * sA;
    Bhi += (size_t)blockIdx.z * sB;  Blo += (size_t)blockIdx.z * sB;

    const int tid  = threadIdx.x;
    const int lane = tid & 31;
    const int wid  = tid >> 5;
    const int bm   = blockIdx.y * 128;
    const int bn   = blockIdx.x * 128;
    const int m_warp = (wid & 3) * 32;
    const int n_warp = (wid >> 2) * 64;

    const uint32_t sbase = smem_u32(smem);

    // ldmatrix per-lane byte offsets within a matrix tile
    const uint32_t aoff = (uint32_t)((m_warp + (lane & 15)) * (LDT * 2) + ((lane >> 4) * 8) * 2);
    const uint32_t boff = (uint32_t)((n_warp + (lane & 7) + ((lane & 16) ? 8 : 0)) * (LDT * 2)
                                     + ((lane & 8) ? 8 : 0) * 2);

    float acc[2][8][4];
    #pragma unroll
    for (int t = 0; t < 2; t++)
        #pragma unroll
        for (int n = 0; n < 8; n++)
            #pragma unroll
            for (int q = 0; q < 4; q++) acc[t][n][q] = 0.0f;

    const int nk = K / KC;

    // cp.async issue of one chunk into one stage buffer.
    // Per matrix: 128 rows x 8 x 16B chunks = 1024; 256 threads x 4 iters.
    auto issue = [&](int buf, int c) {
        const int k0 = c * KC;
        const uint32_t sb = sbase + buf * STAGE_B;
        #pragma unroll
        for (int i = 0; i < 4; i++) {
            const int l   = tid + i * 256;
            const int row = l >> 3;
            const int ch  = (l & 7) * 16;      // byte offset within 128B row data
            const uint32_t soff = (uint32_t)(row * (LDT * 2)) + ch;
            const size_t ga = (size_t)(bm + row) * lda + k0;
            const size_t gb = (size_t)(bn + row) * ldb + k0;
            cpasync16(sb + 0 * MAT_B + soff, (const char*)(Ahi + ga) + ch);
            cpasync16(sb + 1 * MAT_B + soff, (const char*)(Alo + ga) + ch);
            cpasync16(sb + 2 * MAT_B + soff, (const char*)(Bhi + gb) + ch);
            cpasync16(sb + 3 * MAT_B + soff, (const char*)(Blo + gb) + ch);
        }
    };

    auto compute = [&](int buf) {
        const uint32_t base = sbase + buf * STAGE_B;
        #pragma unroll
        for (int ks = 0; ks < 4; ks++) {
            const uint32_t kb = ks * 32;           // 16 bf16 = 32 B
            uint32_t ah[2][4], al[2][4], bh[4][4], bl[4][4];
            #pragma unroll
            for (int t = 0; t < 2; t++) {
                ldsm4(ah[t][0], ah[t][1], ah[t][2], ah[t][3],
                      base + 0 * MAT_B + aoff + t * (16 * LDT * 2) + kb);
                ldsm4(al[t][0], al[t][1], al[t][2], al[t][3],
                      base + 1 * MAT_B + aoff + t * (16 * LDT * 2) + kb);
            }
            #pragma unroll
            for (int u = 0; u < 4; u++) {
                ldsm4(bh[u][0], bh[u][1], bh[u][2], bh[u][3],
                      base + 2 * MAT_B + boff + u * (16 * LDT * 2) + kb);
                ldsm4(bl[u][0], bl[u][1], bl[u][2], bl[u][3],
                      base + 3 * MAT_B + boff + u * (16 * LDT * 2) + kb);
            }
            #pragma unroll
            for (int t = 0; t < 2; t++)
                #pragma unroll
                for (int n = 0; n < 8; n++) {
                    const uint32_t* fh = &bh[n >> 1][(n & 1) * 2];
                    const uint32_t* fl = &bl[n >> 1][(n & 1) * 2];
                    mma16816(acc[t][n], ah[t], fh);   // hi*hi
                    mma16816(acc[t][n], ah[t], fl);   // hi*lo
                    mma16816(acc[t][n], al[t], fh);   // lo*hi
                }
        }
    };

    // ---- 3-stage pipeline ----
    issue(0, 0);
    asm volatile("cp.async.commit_group;" ::: "memory");
    issue(1, 1);
    asm volatile("cp.async.commit_group;" ::: "memory");

    for (int c = 0; c < nk; ++c) {
        if (c + 2 < nk) issue((c + 2) % 3, c + 2);
        asm volatile("cp.async.commit_group;" ::: "memory");
        asm volatile("cp.async.wait_group 2;" ::: "memory");
        __syncthreads();
        compute(c % 3);
        __syncthreads();
    }

    // ---- epilogue ----
    #pragma unroll
    for (int t = 0; t < 2; t++)
        #pragma unroll
        for (int n = 0; n < 8; n++) {
            const int row = bm + m_warp + t * 16 + (lane >> 2);
            const int col = bn + n_warp + n * 8 + (lane & 3) * 2;
            if (mode == 0) {
                float* C0 = Cf + (size_t)blockIdx.z * sC;
                *(float2*)(C0 + (size_t)row * ldc + col) =
                    make_float2(acc[t][n][0], acc[t][n][1]);
                *(float2*)(C0 + (size_t)(row + 8) * ldc + col) =
                    make_float2(acc[t][n][2], acc[t][n][3]);
            } else if (mode == 1) {
                bf162 h, l;
                split2(acc[t][n][0], acc[t][n][1], h, l);
                *(bf162*)(Chi + (size_t)row * ldc + col) = h;
                *(bf162*)(Clo + (size_t)row * ldc + col) = l;
                split2(acc[t][n][2], acc[t][n][3], h, l);
                *(bf162*)(Chi + (size_t)(row + 8) * ldc + col) = h;
                *(bf162*)(Clo + (size_t)(row + 8) * ldc + col) = l;
            } else {
                #pragma unroll
                for (int q = 0; q < 4; q++) {
                    const int r = row + (q >> 1) * 8;
                    const int cc = col + (q & 1);
                    bf16 h = __float2bfloat16_rn(acc[t][n][q]);
                    bf16 l = __float2bfloat16_rn(acc[t][n][q] - __bfloat162float(h));
                    Chi[(size_t)cc * ldc + r] = h;
                    Clo[(size_t)cc * ldc + r] = l;
                }
            }
        }
}

// ---------------------------------------------------------------------------
// Row softmax over 4096 fp32 scores -> bf16 hi/lo probabilities.
// One block (256 threads) per row.
// ---------------------------------------------------------------------------
__global__ __launch_bounds__(256) void softmax_split_kernel(
    const float* __restrict__ Sm, bf16* __restrict__ Phi, bf16* __restrict__ Plo)
{
    const float* row = Sm + (size_t)blockIdx.x * SLEN;
    bf16* ph = Phi + (size_t)blockIdx.x * SLEN;
    bf16* pl = Plo + (size_t)blockIdx.x * SLEN;
    const int t    = threadIdx.x;
    const int lane = t & 31;
    const int warp = t >> 5;

    __shared__ float red[8];

    float v[16];
    float mx = -1e30f;
    #pragma unroll
    for (int i = 0; i < 16; i++) {
        v[i] = row[t + (i << 8)];
        mx = fmaxf(mx, v[i]);
    }
    #pragma unroll
    for (int o = 16; o > 0; o >>= 1)
        mx = fmaxf(mx, __shfl_xor_sync(0xffffffffu, mx, o));
    if (lane == 0) red[warp] = mx;
    __syncthreads();
    float rmax = red[0];
    #pragma unroll
    for (int i = 1; i < 8; i++) rmax = fmaxf(rmax, red[i]);

    float sum = 0.0f;
    #pragma unroll
    for (int i = 0; i < 16; i++) {
        v[i] = __expf(v[i] - rmax);
        sum += v[i];
    }
    #pragma unroll
    for (int o = 16; o > 0; o >>= 1)
        sum += __shfl_xor_sync(0xffffffffu, sum, o);
    __syncthreads();
    if (lane == 0) red[warp] = sum;
    __syncthreads();
    float rsum = 0.0f;
    #pragma unroll
    for (int i = 0; i < 8; i++) rsum += red[i];

    const float inv = 1.0f / rsum;
    #pragma unroll
    for (int i = 0; i < 16; i++) {
        float p = v[i] * inv;
        bf16 h = __float2bfloat16_rn(p);
        ph[t + (i << 8)] = h;
        pl[t + (i << 8)] = __float2bfloat16_rn(p - __bfloat162float(h));
    }
}

// ---------------------------------------------------------------------------
// Final epilogue: y = attended + x;  out = y / ||y||_2 per 1024-row.
// ---------------------------------------------------------------------------
__global__ __launch_bounds__(256) void epilogue_kernel(
    const float* __restrict__ x, float* __restrict__ out)
{
    const size_t base = (size_t)blockIdx.x * DDIM;
    const int t    = threadIdx.x;
    const int lane = t & 31;
    const int warp = t >> 5;

    __shared__ float red[8];

    float4 a  = *(const float4*)(out + base + t * 4);
    float4 xv = *(const float4*)(x   + base + t * 4);
    float y0 = a.x + xv.x, y1 = a.y + xv.y, y2 = a.z + xv.z, y3 = a.w + xv.w;

    float ss = y0 * y0 + y1 * y1 + y2 * y2 + y3 * y3;
    #pragma unroll
    for (int o = 16; o > 0; o >>= 1)
        ss += __shfl_xor_sync(0xffffffffu, ss, o);
    if (lane == 0) red[warp] = ss;
    __syncthreads();
    float tot = 0.0f;
    #pragma unroll
    for (int i = 0; i < 8; i++) tot += red[i];

    const float inv = 1.0f / sqrtf(tot);
    *(float4*)(out + base + t * 4) =
        make_float4(y0 * inv, y1 * inv, y2 * inv, y3 * inv);
}

// ---------------------------------------------------------------------------
// Launch
// ---------------------------------------------------------------------------
extern "C" void kernel_launch(void* const* d_in, const int* in_sizes, int n_in,
                              void* d_out, int out_size)
{
    const float* x  = (const float*)d_in[0];
    const float* Wq = (const float*)d_in[1];
    const float* Wk = (const float*)d_in[2];
    const float* Wv = (const float*)d_in[3];
    float* out = (float*)d_out;

    bf16 *xhi, *xlo, *Wqhi, *Wqlo, *Wkhi, *Wklo, *Wvhi, *Wvlo;
    bf16 *Qhi, *Qlo, *Khi, *Klo, *Vthi, *Vtlo, *Phi, *Plo;
    float* Sc;
    cudaGetSymbolAddress((void**)&xhi,  g_xhi);   cudaGetSymbolAddress((void**)&xlo,  g_xlo);
    cudaGetSymbolAddress((void**)&Wqhi, g_Wqhi);  cudaGetSymbolAddress((void**)&Wqlo, g_Wqlo);
    cudaGetSymbolAddress((void**)&Wkhi, g_Wkhi);  cudaGetSymbolAddress((void**)&Wklo, g_Wklo);
    cudaGetSymbolAddress((void**)&Wvhi, g_Wvhi);  cudaGetSymbolAddress((void**)&Wvlo, g_Wvlo);
    cudaGetSymbolAddress((void**)&Qhi,  g_Qhi);   cudaGetSymbolAddress((void**)&Qlo,  g_Qlo);
    cudaGetSymbolAddress((void**)&Khi,  g_Khi);   cudaGetSymbolAddress((void**)&Klo,  g_Klo);
    cudaGetSymbolAddress((void**)&Vthi, g_Vthi);  cudaGetSymbolAddress((void**)&Vtlo, g_Vtlo);
    cudaGetSymbolAddress((void**)&Phi,  g_Phi);   cudaGetSymbolAddress((void**)&Plo,  g_Plo);
    cudaGetSymbolAddress((void**)&Sc,   g_S);

    cudaFuncSetAttribute(gemm_bf, cudaFuncAttributeMaxDynamicSharedMemorySize, SMEM_DYN);

    const size_t sQKV = (size_t)SLEN * DDIM;
    const size_t sSS  = (size_t)SLEN * SLEN;
    dim3 blk(256);

    // 0) split inputs to bf16 hi/lo
    conv_split<<<(MTOT * DDIM) / 1024, blk>>>(x,  xhi,  xlo);
    conv_split<<<(DDIM * DDIM) / 1024, blk>>>(Wq, Wqhi, Wqlo);
    conv_split<<<(DDIM * DDIM) / 1024, blk>>>(Wk, Wkhi, Wklo);
    conv_split<<<(DDIM * DDIM) / 1024, blk>>>(Wv, Wvhi, Wvlo);

    // 1) projections (NT): Q/K as hi/lo pairs; V written transposed hi/lo
    dim3 gqkv(DDIM / 128, MTOT / 128, 1);
    gemm_bf<<<gqkv, blk, SMEM_DYN>>>(xhi, xlo, Wqhi, Wqlo, nullptr, Qhi, Qlo,
                                     DDIM, DDIM, DDIM, DDIM, 1, 0, 0, 0);
    gemm_bf<<<gqkv, blk, SMEM_DYN>>>(xhi, xlo, Wkhi, Wklo, nullptr, Khi, Klo,
                                     DDIM, DDIM, DDIM, DDIM, 1, 0, 0, 0);
    gemm_bf<<<gqkv, blk, SMEM_DYN>>>(xhi, xlo, Wvhi, Wvlo, nullptr, Vthi, Vtlo,
                                     DDIM, DDIM, MTOT, DDIM, 2, 0, 0, 0);

    // 2) scores = Q @ K^T per batch (fp32 out)
    dim3 gsc(SLEN / 128, SLEN / 128, BATCH);
    gemm_bf<<<gsc, blk, SMEM_DYN>>>(Qhi, Qlo, Khi, Klo, Sc, nullptr, nullptr,
                                    DDIM, DDIM, SLEN, DDIM, 0, sQKV, sQKV, sSS);

    // 3) softmax -> P hi/lo (BETA = 1)
    softmax_split_kernel<<<MTOT, blk>>>(Sc, Phi, Plo);

    // 4) attended = P @ Vt^T per batch (fp32 out into d_out)
    dim3 gav(DDIM / 128, SLEN / 128, BATCH);
    gemm_bf<<<gav, blk, SMEM_DYN>>>(Phi, Plo, Vthi, Vtlo, out, nullptr, nullptr,
                                    SLEN, MTOT, DDIM, SLEN, 0,
                                    sSS, (size_t)SLEN, sQKV);

    // 5) y = attended + x; L2 normalize
    epilogue_kernel<<<MTOT, blk>>>(x, out);
}

// round 6
// speedup vs baseline: 2.7521x; 1.0215x over previous
#include <cuda_runtime.h>
#include <cuda_bf16.h>
#include <cstdint>
#include <cstddef>

#define BATCH   4
#define SLEN    4096
#define DDIM    1024
#define MTOT    (BATCH * SLEN)          // 16384

typedef __nv_bfloat16  bf16;
typedef __nv_bfloat162 bf162;

// ---------------------------------------------------------------------------
// Scratch (allocation-free rule: __device__ globals). All operands pre-split
// into bf16 hi/lo pairs so GEMM mainloops are pure bf16.
// ---------------------------------------------------------------------------
__device__ bf16 g_xhi [(size_t)MTOT * DDIM];
__device__ bf16 g_xlo [(size_t)MTOT * DDIM];
__device__ bf16 g_Wqhi[(size_t)DDIM * DDIM];
__device__ bf16 g_Wqlo[(size_t)DDIM * DDIM];
__device__ bf16 g_Wkhi[(size_t)DDIM * DDIM];
__device__ bf16 g_Wklo[(size_t)DDIM * DDIM];
__device__ bf16 g_Wvhi[(size_t)DDIM * DDIM];
__device__ bf16 g_Wvlo[(size_t)DDIM * DDIM];
__device__ bf16 g_Qhi [(size_t)MTOT * DDIM];
__device__ bf16 g_Qlo [(size_t)MTOT * DDIM];
__device__ bf16 g_Khi [(size_t)MTOT * DDIM];
__device__ bf16 g_Klo [(size_t)MTOT * DDIM];
__device__ bf16 g_Vthi[(size_t)DDIM * MTOT];   // V transposed [D, MTOT]
__device__ bf16 g_Vtlo[(size_t)DDIM * MTOT];
__device__ float g_S  [(size_t)MTOT * SLEN];   // fp32 scores (softmax input)
__device__ bf16 g_Phi [(size_t)MTOT * SLEN];
__device__ bf16 g_Plo [(size_t)MTOT * SLEN];

// ---------------------------------------------------------------------------
// Helpers (arch-agnostic PTX only: plain sm_103 target)
// ---------------------------------------------------------------------------
__device__ __forceinline__ uint32_t smem_u32(const void* p) {
    uint32_t a;
    asm("{ .reg .u64 t; cvta.to.shared.u64 t, %1; cvt.u32.u64 %0, t; }" : "=r"(a) : "l"(p));
    return a;
}
__device__ __forceinline__ void ldsm4(uint32_t& r0, uint32_t& r1, uint32_t& r2, uint32_t& r3,
                                      uint32_t addr) {
    asm volatile("ldmatrix.sync.aligned.m8n8.x4.shared.b16 {%0,%1,%2,%3}, [%4];"
                 : "=r"(r0), "=r"(r1), "=r"(r2), "=r"(r3) : "r"(addr));
}
__device__ __forceinline__ void mma16816(float* c, const uint32_t* a, const uint32_t* b) {
    asm volatile(
        "mma.sync.aligned.m16n8k16.row.col.f32.bf16.bf16.f32 "
        "{%0,%1,%2,%3}, {%4,%5,%6,%7}, {%8,%9}, {%0,%1,%2,%3};"
        : "+f"(c[0]), "+f"(c[1]), "+f"(c[2]), "+f"(c[3])
        : "r"(a[0]), "r"(a[1]), "r"(a[2]), "r"(a[3]), "r"(b[0]), "r"(b[1]));
}
__device__ __forceinline__ void cpasync16(uint32_t dst, const void* src) {
    asm volatile("cp.async.cg.shared.global [%0], [%1], 16;" :: "r"(dst), "l"(src));
}
__device__ __forceinline__ void split2(float x, float y, bf162& h, bf162& l) {
    h = __floats2bfloat162_rn(x, y);
    float2 f = __bfloat1622float2(h);
    l = __floats2bfloat162_rn(x - f.x, y - f.y);
}

// ---------------------------------------------------------------------------
// fp32 -> bf16 hi/lo split (elementwise). n divisible by 1024.
// ---------------------------------------------------------------------------
__global__ __launch_bounds__(256) void conv_split(
    const float* __restrict__ src, bf16* __restrict__ hi, bf16* __restrict__ lo)
{
    size_t i = ((size_t)blockIdx.x * 256 + threadIdx.x) * 4;
    float4 v = *(const float4*)(src + i);
    bf162 h0, l0, h1, l1;
    split2(v.x, v.y, h0, l0);
    split2(v.z, v.w, h1, l1);
    *(bf162*)(hi + i)     = h0;
    *(bf162*)(hi + i + 2) = h1;
    *(bf162*)(lo + i)     = l0;
    *(bf162*)(lo + i + 2) = l1;
}

// ---------------------------------------------------------------------------
// Pure-bf16 NT GEMM (3-pass fp32 emulation): C = sum_k A[m,k]*B[n,k]
// Tile 128x128, K-chunk 64, 3-stage cp.async pipeline, fragment double-buffer,
// one __syncthreads per chunk. 256 threads.
// mode 0: fp32 C.  mode 1: bf16 hi/lo row-major.  mode 2: bf16 hi/lo transposed.
// ---------------------------------------------------------------------------
#define KC       64
#define LDT      72                         // padded row stride (bf16) -> 144 B
#define MAT_B    (128 * LDT * 2)            // 18432 B
#define STAGE_B  (4 * MAT_B)                // Ahi, Alo, Bhi, Blo = 73728 B
#define NSTAGE   3
#define SMEM_DYN (NSTAGE * STAGE_B)         // 221184 B

__global__ __launch_bounds__(256, 1) void gemm_bf(
    const bf16* __restrict__ Ahi, const bf16* __restrict__ Alo,
    const bf16* __restrict__ Bhi, const bf16* __restrict__ Blo,
    float* __restrict__ Cf, bf16* __restrict__ Chi, bf16* __restrict__ Clo,
    int lda, int ldb, int ldc, int K, int mode,
    size_t sA, size_t sB, size_t sC)
{
    extern __shared__ char smem[];
    Ahi += (size_t)blockIdx.z * sA;  Alo += (size_t)blockIdx.z * sA;
    Bhi += (size_t)blockIdx.z * sB;  Blo += (size_t)blockIdx.z * sB;

    const int tid  = threadIdx.x;
    const int lane = tid & 31;
    const int wid  = tid >> 5;
    const int bm   = blockIdx.y * 128;
    const int bn   = blockIdx.x * 128;
    const int m_warp = (wid & 3) * 32;
    const int n_warp = (wid >> 2) * 64;

    const uint32_t sbase = smem_u32(smem);

    // ldmatrix per-lane byte offsets within a matrix tile
    const uint32_t aoff = (uint32_t)((m_warp + (lane & 15)) * (LDT * 2) + ((lane >> 4) * 8) * 2);
    const uint32_t boff = (uint32_t)((n_warp + (lane & 7) + ((lane & 16) ? 8 : 0)) * (LDT * 2)
                                     + ((lane & 8) ? 8 : 0) * 2);

    float acc[2][8][4];
    #pragma unroll
    for (int t = 0; t < 2; t++)
        #pragma unroll
        for (int n = 0; n < 8; n++)
            #pragma unroll
            for (int q = 0; q < 4; q++) acc[t][n][q] = 0.0f;

    const int nk = K / KC;

    // cp.async issue of one chunk into one stage buffer.
    auto issue = [&](int buf, int c) {
        const int k0 = c * KC;
        const uint32_t sb = sbase + buf * STAGE_B;
        #pragma unroll
        for (int i = 0; i < 4; i++) {
            const int l   = tid + i * 256;
            const int row = l >> 3;
            const int ch  = (l & 7) * 16;
            const uint32_t soff = (uint32_t)(row * (LDT * 2)) + ch;
            const size_t ga = (size_t)(bm + row) * lda + k0;
            const size_t gb = (size_t)(bn + row) * ldb + k0;
            cpasync16(sb + 0 * MAT_B + soff, (const char*)(Ahi + ga) + ch);
            cpasync16(sb + 1 * MAT_B + soff, (const char*)(Alo + ga) + ch);
            cpasync16(sb + 2 * MAT_B + soff, (const char*)(Bhi + gb) + ch);
            cpasync16(sb + 3 * MAT_B + soff, (const char*)(Blo + gb) + ch);
        }
    };

    // fragment load for one ks (16-K slab)
    auto ldfr = [&](uint32_t base, int ks,
                    uint32_t (&ah)[2][4], uint32_t (&al)[2][4],
                    uint32_t (&bh)[4][4], uint32_t (&bl)[4][4]) {
        const uint32_t kb = (uint32_t)ks * 32;
        #pragma unroll
        for (int t = 0; t < 2; t++) {
            ldsm4(ah[t][0], ah[t][1], ah[t][2], ah[t][3],
                  base + 0 * MAT_B + aoff + t * (16 * LDT * 2) + kb);
            ldsm4(al[t][0], al[t][1], al[t][2], al[t][3],
                  base + 1 * MAT_B + aoff + t * (16 * LDT * 2) + kb);
        }
        #pragma unroll
        for (int u = 0; u < 4; u++) {
            ldsm4(bh[u][0], bh[u][1], bh[u][2], bh[u][3],
                  base + 2 * MAT_B + boff + u * (16 * LDT * 2) + kb);
            ldsm4(bl[u][0], bl[u][1], bl[u][2], bl[u][3],
                  base + 3 * MAT_B + boff + u * (16 * LDT * 2) + kb);
        }
    };

    auto domma = [&](uint32_t (&ah)[2][4], uint32_t (&al)[2][4],
                     uint32_t (&bh)[4][4], uint32_t (&bl)[4][4]) {
        #pragma unroll
        for (int t = 0; t < 2; t++)
            #pragma unroll
            for (int n = 0; n < 8; n++) {
                const uint32_t* fh = &bh[n >> 1][(n & 1) * 2];
                const uint32_t* fl = &bl[n >> 1][(n & 1) * 2];
                mma16816(acc[t][n], ah[t], fh);   // hi*hi
                mma16816(acc[t][n], ah[t], fl);   // hi*lo
                mma16816(acc[t][n], al[t], fh);   // lo*hi
            }
    };

    // compute one chunk (4 ks-slabs) with 2-deep fragment pipeline
    auto compute = [&](int buf) {
        const uint32_t base = sbase + buf * STAGE_B;
        uint32_t ah[2][2][4], al[2][2][4], bh[2][4][4], bl[2][4][4];
        ldfr(base, 0, ah[0], al[0], bh[0], bl[0]);
        #pragma unroll
        for (int ks = 0; ks < 4; ks++) {
            const int cur = ks & 1, nxt = cur ^ 1;
            if (ks < 3) ldfr(base, ks + 1, ah[nxt], al[nxt], bh[nxt], bl[nxt]);
            domma(ah[cur], al[cur], bh[cur], bl[cur]);
        }
    };

    // ---- pipeline: one barrier per chunk ----
    issue(0, 0);
    asm volatile("cp.async.commit_group;" ::: "memory");
    issue(1, 1);
    asm volatile("cp.async.commit_group;" ::: "memory");

    for (int c = 0; c < nk; ++c) {
        asm volatile("cp.async.wait_group 1;" ::: "memory");
        __syncthreads();
        if (c + 2 < nk) issue((c + 2) % 3, c + 2);
        asm volatile("cp.async.commit_group;" ::: "memory");
        compute(c % 3);
    }

    // ---- epilogue ----
    #pragma unroll
    for (int t = 0; t < 2; t++)
        #pragma unroll
        for (int n = 0; n < 8; n++) {
            const int row = bm + m_warp + t * 16 + (lane >> 2);
            const int col = bn + n_warp + n * 8 + (lane & 3) * 2;
            if (mode == 0) {
                float* C0 = Cf + (size_t)blockIdx.z * sC;
                *(float2*)(C0 + (size_t)row * ldc + col) =
                    make_float2(acc[t][n][0], acc[t][n][1]);
                *(float2*)(C0 + (size_t)(row + 8) * ldc + col) =
                    make_float2(acc[t][n][2], acc[t][n][3]);
            } else if (mode == 1) {
                bf162 h, l;
                split2(acc[t][n][0], acc[t][n][1], h, l);
                *(bf162*)(Chi + (size_t)row * ldc + col) = h;
                *(bf162*)(Clo + (size_t)row * ldc + col) = l;
                split2(acc[t][n][2], acc[t][n][3], h, l);
                *(bf162*)(Chi + (size_t)(row + 8) * ldc + col) = h;
                *(bf162*)(Clo + (size_t)(row + 8) * ldc + col) = l;
            } else {
                #pragma unroll
                for (int q = 0; q < 4; q++) {
                    const int r  = row + (q >> 1) * 8;
                    const int cc = col + (q & 1);
                    bf16 h = __float2bfloat16_rn(acc[t][n][q]);
                    bf16 l = __float2bfloat16_rn(acc[t][n][q] - __bfloat162float(h));
                    Chi[(size_t)cc * ldc + r] = h;
                    Clo[(size_t)cc * ldc + r] = l;
                }
            }
        }
}

// ---------------------------------------------------------------------------
// Row softmax over 4096 fp32 scores -> bf16 hi/lo probabilities.
// ---------------------------------------------------------------------------
__global__ __launch_bounds__(256) void softmax_split_kernel(
    const float* __restrict__ Sm, bf16* __restrict__ Phi, bf16* __restrict__ Plo)
{
    const float* row = Sm + (size_t)blockIdx.x * SLEN;
    bf16* ph = Phi + (size_t)blockIdx.x * SLEN;
    bf16* pl = Plo + (size_t)blockIdx.x * SLEN;
    const int t    = threadIdx.x;
    const int lane = t & 31;
    const int warp = t >> 5;

    __shared__ float red[8];

    float v[16];
    float mx = -1e30f;
    #pragma unroll
    for (int i = 0; i < 16; i++) {
        v[i] = row[t + (i << 8)];
        mx = fmaxf(mx, v[i]);
    }
    #pragma unroll
    for (int o = 16; o > 0; o >>= 1)
        mx = fmaxf(mx, __shfl_xor_sync(0xffffffffu, mx, o));
    if (lane == 0) red[warp] = mx;
    __syncthreads();
    float rmax = red[0];
    #pragma unroll
    for (int i = 1; i < 8; i++) rmax = fmaxf(rmax, red[i]);

    float sum = 0.0f;
    #pragma unroll
    for (int i = 0; i < 16; i++) {
        v[i] = __expf(v[i] - rmax);
        sum += v[i];
    }
    #pragma unroll
    for (int o = 16; o > 0; o >>= 1)
        sum += __shfl_xor_sync(0xffffffffu, sum, o);
    __syncthreads();
    if (lane == 0) red[warp] = sum;
    __syncthreads();
    float rsum = 0.0f;
    #pragma unroll
    for (int i = 0; i < 8; i++) rsum += red[i];

    const float inv = 1.0f / rsum;
    #pragma unroll
    for (int i = 0; i < 16; i++) {
        float p = v[i] * inv;
        bf16 h = __float2bfloat16_rn(p);
        ph[t + (i << 8)] = h;
        pl[t + (i << 8)] = __float2bfloat16_rn(p - __bfloat162float(h));
    }
}

// ---------------------------------------------------------------------------
// Final epilogue: y = attended + x;  out = y / ||y||_2 per 1024-row.
// ---------------------------------------------------------------------------
__global__ __launch_bounds__(256) void epilogue_kernel(
    const float* __restrict__ x, float* __restrict__ out)
{
    const size_t base = (size_t)blockIdx.x * DDIM;
    const int t    = threadIdx.x;
    const int lane = t & 31;
    const int warp = t >> 5;

    __shared__ float red[8];

    float4 a  = *(const float4*)(out + base + t * 4);
    float4 xv = *(const float4*)(x   + base + t * 4);
    float y0 = a.x + xv.x, y1 = a.y + xv.y, y2 = a.z + xv.z, y3 = a.w + xv.w;

    float ss = y0 * y0 + y1 * y1 + y2 * y2 + y3 * y3;
    #pragma unroll
    for (int o = 16; o > 0; o >>= 1)
        ss += __shfl_xor_sync(0xffffffffu, ss, o);
    if (lane == 0) red[warp] = ss;
    __syncthreads();
    float tot = 0.0f;
    #pragma unroll
    for (int i = 0; i < 8; i++) tot += red[i];

    const float inv = 1.0f / sqrtf(tot);
    *(float4*)(out + base + t * 4) =
        make_float4(y0 * inv, y1 * inv, y2 * inv, y3 * inv);
}

// ---------------------------------------------------------------------------
// Launch
// ---------------------------------------------------------------------------
extern "C" void kernel_launch(void* const* d_in, const int* in_sizes, int n_in,
                              void* d_out, int out_size)
{
    const float* x  = (const float*)d_in[0];
    const float* Wq = (const float*)d_in[1];
    const float* Wk = (const float*)d_in[2];
    const float* Wv = (const float*)d_in[3];
    float* out = (float*)d_out;

    bf16 *xhi, *xlo, *Wqhi, *Wqlo, *Wkhi, *Wklo, *Wvhi, *Wvlo;
    bf16 *Qhi, *Qlo, *Khi, *Klo, *Vthi, *Vtlo, *Phi, *Plo;
    float* Sc;
    cudaGetSymbolAddress((void**)&xhi,  g_xhi);   cudaGetSymbolAddress((void**)&xlo,  g_xlo);
    cudaGetSymbolAddress((void**)&Wqhi, g_Wqhi);  cudaGetSymbolAddress((void**)&Wqlo, g_Wqlo);
    cudaGetSymbolAddress((void**)&Wkhi, g_Wkhi);  cudaGetSymbolAddress((void**)&Wklo, g_Wklo);
    cudaGetSymbolAddress((void**)&Wvhi, g_Wvhi);  cudaGetSymbolAddress((void**)&Wvlo, g_Wvlo);
    cudaGetSymbolAddress((void**)&Qhi,  g_Qhi);   cudaGetSymbolAddress((void**)&Qlo,  g_Qlo);
    cudaGetSymbolAddress((void**)&Khi,  g_Khi);   cudaGetSymbolAddress((void**)&Klo,  g_Klo);
    cudaGetSymbolAddress((void**)&Vthi, g_Vthi);  cudaGetSymbolAddress((void**)&Vtlo, g_Vtlo);
    cudaGetSymbolAddress((void**)&Phi,  g_Phi);   cudaGetSymbolAddress((void**)&Plo,  g_Plo);
    cudaGetSymbolAddress((void**)&Sc,   g_S);

    cudaFuncSetAttribute(gemm_bf, cudaFuncAttributeMaxDynamicSharedMemorySize, SMEM_DYN);

    const size_t sQKV = (size_t)SLEN * DDIM;
    const size_t sSS  = (size_t)SLEN * SLEN;
    dim3 blk(256);

    // 0) split inputs to bf16 hi/lo
    conv_split<<<(MTOT * DDIM) / 1024, blk>>>(x,  xhi,  xlo);
    conv_split<<<(DDIM * DDIM) / 1024, blk>>>(Wq, Wqhi, Wqlo);
    conv_split<<<(DDIM * DDIM) / 1024, blk>>>(Wk, Wkhi, Wklo);
    conv_split<<<(DDIM * DDIM) / 1024, blk>>>(Wv, Wvhi, Wvlo);

    // 1) projections (NT): Q/K as hi/lo pairs; V written transposed hi/lo
    dim3 gqkv(DDIM / 128, MTOT / 128, 1);
    gemm_bf<<<gqkv, blk, SMEM_DYN>>>(xhi, xlo, Wqhi, Wqlo, nullptr, Qhi, Qlo,
                                     DDIM, DDIM, DDIM, DDIM, 1, 0, 0, 0);
    gemm_bf<<<gqkv, blk, SMEM_DYN>>>(xhi, xlo, Wkhi, Wklo, nullptr, Khi, Klo,
                                     DDIM, DDIM, DDIM, DDIM, 1, 0, 0, 0);
    gemm_bf<<<gqkv, blk, SMEM_DYN>>>(xhi, xlo, Wvhi, Wvlo, nullptr, Vthi, Vtlo,
                                     DDIM, DDIM, MTOT, DDIM, 2, 0, 0, 0);

    // 2) scores = Q @ K^T per batch (fp32 out)
    dim3 gsc(SLEN / 128, SLEN / 128, BATCH);
    gemm_bf<<<gsc, blk, SMEM_DYN>>>(Qhi, Qlo, Khi, Klo, Sc, nullptr, nullptr,
                                    DDIM, DDIM, SLEN, DDIM, 0, sQKV, sQKV, sSS);

    // 3) softmax -> P hi/lo (BETA = 1)
    softmax_split_kernel<<<MTOT, blk>>>(Sc, Phi, Plo);

    // 4) attended = P @ Vt^T per batch (fp32 out into d_out)
    dim3 gav(DDIM / 128, SLEN / 128, BATCH);
    gemm_bf<<<gav, blk, SMEM_DYN>>>(Phi, Plo, Vthi, Vtlo, out, nullptr, nullptr,
                                    SLEN, MTOT, DDIM, SLEN, 0,
                                    sSS, (size_t)SLEN, sQKV);

    // 5) y = attended + x; L2 normalize
    epilogue_kernel<<<MTOT, blk>>>(x, out);
}